// round 12
// baseline (speedup 1.0000x reference)
#include <cuda_runtime.h>

#define L2E 1.4426950408889634f

static constexpr int Bc = 2, Cc = 8, Hc = 1088, Wc = 1920;
static constexpr int TW = 64, TH = 16, HALO = 4;       // dilation=2, radius=2 -> halo 4
static constexpr int RW = TW + 2 * HALO;               // 72
static constexpr int RH = TH + 2 * HALO;               // 24
static constexpr int S2W = 96;                         // padded slot width for S-pair layout
// sA(float4) + sB(float4) + S2(float2*S2W) + consts
static constexpr int SMEM_BYTES = RH * RW * 32 + RH * S2W * 8 + 128;

using u64 = unsigned long long;

__device__ __forceinline__ u64 pack2(float lo, float hi) {
    u64 r; asm("mov.b64 %0, {%1, %2};" : "=l"(r) : "f"(lo), "f"(hi)); return r;
}
__device__ __forceinline__ void unpack2(u64 v, float& lo, float& hi) {
    asm("mov.b64 {%0, %1}, %2;" : "=f"(lo), "=f"(hi) : "l"(v));
}
__device__ __forceinline__ u64 fma2(u64 a, u64 b, u64 c) {
    u64 r; asm("fma.rn.f32x2 %0, %1, %2, %3;" : "=l"(r) : "l"(a), "l"(b), "l"(c)); return r;
}
__device__ __forceinline__ u64 mul2(u64 a, u64 b) {
    u64 r; asm("mul.rn.f32x2 %0, %1, %2;" : "=l"(r) : "l"(a), "l"(b)); return r;
}
// in-row bank swizzle for the float4 tiles
__device__ __forceinline__ int sw(int x) { return x ^ ((x & 8) >> 2); }
// bank-exact slot layout for the S-pair array: x = 4m+b -> unique slot whose
// low 4 bits are ((m mod 8)<<1 | (b&1)); lanes' consecutive m -> all 32 banks once.
__device__ __forceinline__ int slot(int x) {
    int m = x >> 2, b = x & 3;
    return (((m >> 3) * 2 + (b >> 1)) << 4) + (((m & 7) << 1) | (b & 1));
}

__device__ float g_rcp[8];   // -p[c]^2 * log2(e)
__device__ float g_lw[25];   // log2(tk[t]) + log2(e)*(sx*dx^2 + sy*dy^2)

__global__ void bf_setup(const float* __restrict__ params,
                         const float* __restrict__ kern) {
    if (threadIdx.x == 0) {
        float p[10];
#pragma unroll
        for (int i = 0; i < 10; i++) p[i] = params[i];
#pragma unroll
        for (int c = 0; c < 8; c++) g_rcp[c] = -p[c] * p[c] * L2E;
        float sx = -p[8] * p[8];
        float sy = -p[9] * p[9];
        float k[25], m = -1e30f;
        for (int i = 0; i < 25; i++) { k[i] = kern[i] * 0.2f; m = fmaxf(m, k[i]); }
        float s = 0.f;
        for (int i = 0; i < 25; i++) { k[i] = expf(k[i] - m); s += k[i]; }
        float inv = 1.0f / s;
        for (int t = 0; t < 25; t++) {
            int ky = t / 5, kx = t % 5;
            float dy = (float)((ky - 2) * 2);
            float dx = (float)((kx - 2) * 2);
            g_lw[t] = log2f(k[t] * inv) + L2E * (sx * dx * dx + sy * dy * dy);
        }
    }
}

template <int DYN>
__global__ __launch_bounds__(256, 2)
void bf_main(const float* __restrict__ inp, float* __restrict__ out) {
    extern __shared__ float smem[];
    float4* sA  = (float4*)smem;                 // channels 0..3 (swizzled in-row)
    float4* sB  = sA + RH * RW;                  // channels 4..7
    float2* sS2 = (float2*)(sB + RH * RW);       // (s[x], s[x+2]) pairs, slot layout
    float*  sLW = (float*)(sS2 + RH * S2W);      // 25 tap constants

    const int b  = blockIdx.z;
    const int x0 = blockIdx.x * TW - HALO;
    const int y0 = blockIdx.y * TH - HALO;

    if (threadIdx.x < 25) sLW[threadIdx.x] = g_lw[threadIdx.x];

    float rc[8];
#pragma unroll
    for (int c = 0; c < 8; c++) rc[c] = g_rcp[c];

    const float* ibase = inp + (size_t)b * Cc * Hc * Wc;

    // ---- cooperative tile load; s written into both pairs it belongs to ----
    for (int i = threadIdx.x; i < RH * RW; i += 256) {
        int ry = i / RW, rx = i - ry * RW;
        int gy = y0 + ry, gx = x0 + rx;
        float v[8];
        float s;
        if ((unsigned)gy < (unsigned)Hc && (unsigned)gx < (unsigned)Wc) {
            const float* p = ibase + gy * Wc + gx;
#pragma unroll
            for (int c = 0; c < 8; c++) v[c] = p[c * Hc * Wc];
            s = 0.f;
#pragma unroll
            for (int c = 0; c < 8; c++) s = fmaf(rc[c] * v[c], v[c], s);
        } else {
#pragma unroll
            for (int c = 0; c < 8; c++) v[c] = 0.f;
            s = -1e30f;   // ex2 -> 0: tap contributes nothing
        }
        int si = ry * RW + sw(rx);
        sA[si] = make_float4(v[0], v[1], v[2], v[3]);
        sB[si] = make_float4(v[4], v[5], v[6], v[7]);
        // s(x) is .x of pair(x) and .y of pair(x-2)
        sS2[ry * S2W + slot(rx)].x = s;
        if (rx >= 2) sS2[ry * S2W + slot(rx - 2)].y = s;
    }

    __syncthreads();

    const ulonglong2* sA2 = (const ulonglong2*)sA;
    const ulonglong2* sB2 = (const ulonglong2*)sB;

    // 2x2 quad per thread: rows (row0, row0+2), cols (c0, c0+2).
    const int l    = threadIdx.x & 31;
    const int rp   = threadIdx.x >> 5;                  // 0..7 (uniform per warp)
    const int c0   = ((l >> 1) << 2) + (l & 1);
    const int row0 = ((rp >> 1) << 2) + (rp & 1);

    int swc[6];
#pragma unroll
    for (int ix = 0; ix < 6; ix++) swc[ix] = sw(c0 + 2 * ix);
    int slc[3];
#pragma unroll
    for (int jj = 0; jj < 3; jj++) slc[jj] = slot(c0 + 4 * jj);

    // centers: pixel(py,px) is record (iy=py+2, ix=px+2)
    u64 q[4][4];
    float sc[4];
#pragma unroll
    for (int py = 0; py < 2; py++)
#pragma unroll
    for (int px = 0; px < 2; px++) {
        const int p = py * 2 + px;
        const int rr = row0 + 2 * (py + 2);
        const int idx = rr * RW + swc[px + 2];
        const ulonglong2 ca = sA2[idx];
        const ulonglong2 cb = sB2[idx];
        const float2 sp = sS2[rr * S2W + slc[1]];   // pair (c0+4, c0+6) = (px=0, px=1)
        sc[p] = (px == 0) ? sp.x : sp.y;
        float a0,a1,a2,a3,b0,b1,b2,b3;
        unpack2(ca.x,a0,a1); unpack2(ca.y,a2,a3);
        unpack2(cb.x,b0,b1); unpack2(cb.y,b2,b3);
        q[p][0] = pack2(rc[0]*a0, rc[1]*a1);
        q[p][1] = pack2(rc[2]*a2, rc[3]*a3);
        q[p][2] = pack2(rc[4]*b0, rc[5]*b1);
        q[p][3] = pack2(rc[6]*b2, rc[7]*b3);
    }

    float den[4] = {0.f, 0.f, 0.f, 0.f};
    float num[4][DYN];
#pragma unroll
    for (int p = 0; p < 4; p++)
#pragma unroll
        for (int c = 0; c < DYN; c++) num[p][c] = 0.f;

#pragma unroll
    for (int iy = 0; iy < 6; iy++) {
        const int rr = row0 + 2 * iy;
        float spair[6];
#pragma unroll
        for (int jj = 0; jj < 3; jj++) {
            const float2 sp = sS2[rr * S2W + slc[jj]];
            spair[2 * jj] = sp.x; spair[2 * jj + 1] = sp.y;
        }
#pragma unroll
        for (int ix = 0; ix < 6; ix++) {
            const int idx = rr * RW + swc[ix];
            const ulonglong2 na = sA2[idx];
            const ulonglong2 nb = sB2[idx];
            const float sn = spair[ix];
            // unpack only the channels needed for num accumulation
            float nv[((DYN + 1) / 2) * 2];
            unpack2(na.x, nv[0], nv[1]);
            if constexpr (DYN > 2) unpack2(na.y, nv[2], nv[3]);
            if constexpr (DYN > 4) unpack2(nb.x, nv[4], nv[5]);
            if constexpr (DYN > 6) unpack2(nb.y, nv[6], nv[7]);

#pragma unroll
            for (int py = 0; py < 2; py++)
#pragma unroll
            for (int px = 0; px < 2; px++) {
                if (iy >= py && iy <= py + 4 && ix >= px && ix <= px + 4) {
                    const int p = py * 2 + px;
                    u64 acc = mul2(q[p][3], nb.y);
                    acc = fma2(q[p][2], nb.x, acc);
                    acc = fma2(q[p][1], na.y, acc);
                    acc = fma2(q[p][0], na.x, acc);
                    float dlo, dhi; unpack2(acc, dlo, dhi);
                    float arg = fmaf(dlo + dhi, -2.0f,
                                     sn + (sc[p] + sLW[(iy - py) * 5 + (ix - px)]));
                    float w;
                    asm("ex2.approx.ftz.f32 %0, %1;" : "=f"(w) : "f"(arg));
                    den[p] += w;
#pragma unroll
                    for (int c = 0; c < DYN; c++) num[p][c] = fmaf(w, nv[c], num[p][c]);
                }
            }
        }
    }

    // exact tiling: no bounds checks needed
    const int gyb = blockIdx.y * TH + row0;
    const int gxb = blockIdx.x * TW + c0;
#pragma unroll
    for (int py = 0; py < 2; py++)
#pragma unroll
    for (int px = 0; px < 2; px++) {
        const int p = py * 2 + px;
        float rd;
        asm("rcp.approx.ftz.f32 %0, %1;" : "=f"(rd) : "f"(den[p]));
        float* op = out + (((size_t)b * DYN) * Hc + (gyb + 2 * py)) * Wc + (gxb + 2 * px);
#pragma unroll
        for (int c = 0; c < DYN; c++) op[(size_t)c * Hc * Wc] = num[p][c] * rd;
    }
}

extern "C" void kernel_launch(void* const* d_in, const int* in_sizes, int n_in,
                              void* d_out, int out_size) {
    const float* inp    = (const float*)d_in[0];
    const float* params = (const float*)d_in[1];
    const float* kern   = (const float*)d_in[2];
    float* out = (float*)d_out;
    (void)in_sizes; (void)n_in;

    int dyn = out_size / (Bc * Hc * Wc);
    if (dyn < 1) dyn = 1;
    if (dyn > 8) dyn = 8;

    bf_setup<<<1, 32>>>(params, kern);

    dim3 grid(Wc / TW, (Hc + TH - 1) / TH, Bc);

#define BF_LAUNCH(D)                                                                     \
    {                                                                                    \
        cudaFuncSetAttribute(bf_main<D>, cudaFuncAttributeMaxDynamicSharedMemorySize,    \
                             SMEM_BYTES);                                                \
        bf_main<D><<<grid, 256, SMEM_BYTES>>>(inp, out);                                 \
    }

    switch (dyn) {
        case 1: BF_LAUNCH(1); break;
        case 2: BF_LAUNCH(2); break;
        case 3: BF_LAUNCH(3); break;
        case 4: BF_LAUNCH(4); break;
        case 5: BF_LAUNCH(5); break;
        case 6: BF_LAUNCH(6); break;
        case 7: BF_LAUNCH(7); break;
        case 8: BF_LAUNCH(8); break;
        default: BF_LAUNCH(3); break;
    }
#undef BF_LAUNCH
}

// round 13
// speedup vs baseline: 1.0207x; 1.0207x over previous
#include <cuda_runtime.h>

#define L2E 1.4426950408889634f

static constexpr int Bc = 2, Cc = 8, Hc = 1088, Wc = 1920;
static constexpr int TW = 64, TH = 16, HALO = 4;       // dilation=2, radius=2 -> halo 4
static constexpr int RW = TW + 2 * HALO;               // 72
static constexpr int RH = TH + 2 * HALO;               // 24
static constexpr int SMEM_BYTES = RH * RW * (16 + 16 + 4) + 32 * 4;

using u64 = unsigned long long;

__device__ __forceinline__ u64 pack2(float lo, float hi) {
    u64 r; asm("mov.b64 %0, {%1, %2};" : "=l"(r) : "f"(lo), "f"(hi)); return r;
}
__device__ __forceinline__ void unpack2(u64 v, float& lo, float& hi) {
    asm("mov.b64 {%0, %1}, %2;" : "=f"(lo), "=f"(hi) : "l"(v));
}
__device__ __forceinline__ u64 fma2(u64 a, u64 b, u64 c) {
    u64 r; asm("fma.rn.f32x2 %0, %1, %2, %3;" : "=l"(r) : "l"(a), "l"(b), "l"(c)); return r;
}
__device__ __forceinline__ u64 mul2(u64 a, u64 b) {
    u64 r; asm("mul.rn.f32x2 %0, %1, %2;" : "=l"(r) : "l"(a), "l"(b)); return r;
}
// in-row bank swizzle: flip bit1 by bit3 so gapped lane patterns hit distinct banks
__device__ __forceinline__ int sw(int x) { return x ^ ((x & 8) >> 2); }

__device__ float g_rcp[8];   // -p[c]^2 * log2(e)
__device__ float g_lw[25];   // log2(tk[t]) + log2(e)*(sx*dx^2 + sy*dy^2)

__global__ void bf_setup(const float* __restrict__ params,
                         const float* __restrict__ kern) {
    if (threadIdx.x == 0) {
        float p[10];
#pragma unroll
        for (int i = 0; i < 10; i++) p[i] = params[i];
#pragma unroll
        for (int c = 0; c < 8; c++) g_rcp[c] = -p[c] * p[c] * L2E;
        float sx = -p[8] * p[8];
        float sy = -p[9] * p[9];
        float k[25], m = -1e30f;
        for (int i = 0; i < 25; i++) { k[i] = kern[i] * 0.2f; m = fmaxf(m, k[i]); }
        float s = 0.f;
        for (int i = 0; i < 25; i++) { k[i] = expf(k[i] - m); s += k[i]; }
        float inv = 1.0f / s;
        for (int t = 0; t < 25; t++) {
            int ky = t / 5, kx = t % 5;
            float dy = (float)((ky - 2) * 2);
            float dx = (float)((kx - 2) * 2);
            g_lw[t] = log2f(k[t] * inv) + L2E * (sx * dx * dx + sy * dy * dy);
        }
    }
}

template <int DYN>
__global__ __launch_bounds__(256, 2)
void bf_main(const float* __restrict__ inp, float* __restrict__ out) {
    extern __shared__ float smem[];
    float4* sA = (float4*)smem;           // channels 0..3 (pixel-major, swizzled in-row)
    float4* sB = sA + RH * RW;            // channels 4..7
    float*  sS = (float*)(sB + RH * RW);  // s = sum_c rc_c * v_c^2  (or -1e30 if OOB)
    float*  sLW = sS + RH * RW;           // 25 tap constants

    const int b  = blockIdx.z;
    const int x0 = blockIdx.x * TW - HALO;
    const int y0 = blockIdx.y * TH - HALO;

    if (threadIdx.x < 25) sLW[threadIdx.x] = g_lw[threadIdx.x];

    float rc[8];
#pragma unroll
    for (int c = 0; c < 8; c++) rc[c] = g_rcp[c];

    const float* ibase = inp + (size_t)b * Cc * Hc * Wc;

    // ---- cooperative tile load (swizzled within row) ----
    for (int i = threadIdx.x; i < RH * RW; i += 256) {
        int ry = i / RW, rx = i - ry * RW;
        int gy = y0 + ry, gx = x0 + rx;
        float v[8];
        float s;
        if ((unsigned)gy < (unsigned)Hc && (unsigned)gx < (unsigned)Wc) {
            const float* p = ibase + gy * Wc + gx;
#pragma unroll
            for (int c = 0; c < 8; c++) v[c] = p[c * Hc * Wc];
            s = 0.f;
#pragma unroll
            for (int c = 0; c < 8; c++) s = fmaf(rc[c] * v[c], v[c], s);
        } else {
#pragma unroll
            for (int c = 0; c < 8; c++) v[c] = 0.f;
            s = -1e30f;   // ex2 -> 0: tap contributes nothing
        }
        int si = ry * RW + sw(rx);
        sA[si] = make_float4(v[0], v[1], v[2], v[3]);
        sB[si] = make_float4(v[4], v[5], v[6], v[7]);
        sS[si] = s;
    }

    __syncthreads();

    const ulonglong2* sA2 = (const ulonglong2*)sA;
    const ulonglong2* sB2 = (const ulonglong2*)sB;

    // 2x2 quad per thread: rows (row0, row0+2), cols (c0, c0+2).
    const int l    = threadIdx.x & 31;
    const int rp   = threadIdx.x >> 5;                  // 0..7
    const int c0   = ((l >> 1) << 2) + (l & 1);
    const int row0 = ((rp >> 1) << 2) + (rp & 1);

    int swc[6];
#pragma unroll
    for (int ix = 0; ix < 6; ix++) swc[ix] = sw(c0 + 2 * ix);

    // centers: pixel(py,px) is record (iy=py+2, ix=px+2)
    u64 q[4][4];
    float sc[4];
#pragma unroll
    for (int py = 0; py < 2; py++)
#pragma unroll
    for (int px = 0; px < 2; px++) {
        const int p = py * 2 + px;
        const int idx = (row0 + 2 * (py + 2)) * RW + swc[px + 2];
        const ulonglong2 ca = sA2[idx];
        const ulonglong2 cb = sB2[idx];
        sc[p] = sS[idx];
        float a0,a1,a2,a3,b0,b1,b2,b3;
        unpack2(ca.x,a0,a1); unpack2(ca.y,a2,a3);
        unpack2(cb.x,b0,b1); unpack2(cb.y,b2,b3);
        q[p][0] = pack2(rc[0]*a0, rc[1]*a1);
        q[p][1] = pack2(rc[2]*a2, rc[3]*a3);
        q[p][2] = pack2(rc[4]*b0, rc[5]*b1);
        q[p][3] = pack2(rc[6]*b2, rc[7]*b3);
    }

    // Accumulators: full channel pairs as f32x2; for odd DYN the last pair is
    // (channel DYN-1, den) -- the hi lane accumulates sum(w)*1 = den for free.
    constexpr int NFULL = DYN / 2;          // full channel pairs
    constexpr bool ODD  = (DYN & 1) != 0;
    constexpr int NACC  = NFULL + (ODD ? 1 : 0);

    u64 numP[4][NACC];
#pragma unroll
    for (int p = 0; p < 4; p++)
#pragma unroll
        for (int f = 0; f < NACC; f++) numP[p][f] = 0ull;
    float den[4] = {0.f, 0.f, 0.f, 0.f};   // used only for even DYN

    const float one = 1.0f;

#pragma unroll
    for (int iy = 0; iy < 6; iy++) {
#pragma unroll
        for (int ix = 0; ix < 6; ix++) {
            const int idx = (row0 + 2 * iy) * RW + swc[ix];
            const ulonglong2 na = sA2[idx];
            const ulonglong2 nb = sB2[idx];
            const float sn = sS[idx];
            const u64 halves[4] = {na.x, na.y, nb.x, nb.y};

            // tail operand (channel DYN-1 paired with 1.0) -- shared by all 4 pixels
            u64 tailv = 0ull;
            if constexpr (ODD) {
                float tl, th; unpack2(halves[NFULL], tl, th); (void)th;
                tailv = pack2(tl, one);
            }

#pragma unroll
            for (int py = 0; py < 2; py++)
#pragma unroll
            for (int px = 0; px < 2; px++) {
                if (iy >= py && iy <= py + 4 && ix >= px && ix <= px + 4) {
                    const int p = py * 2 + px;
                    u64 acc = mul2(q[p][3], nb.y);
                    acc = fma2(q[p][2], nb.x, acc);
                    acc = fma2(q[p][1], na.y, acc);
                    acc = fma2(q[p][0], na.x, acc);
                    float dlo, dhi; unpack2(acc, dlo, dhi);
                    float arg = fmaf(dlo + dhi, -2.0f,
                                     sn + (sc[p] + sLW[(iy - py) * 5 + (ix - px)]));
                    float w;
                    asm("ex2.approx.ftz.f32 %0, %1;" : "=f"(w) : "f"(arg));
                    const u64 w2 = pack2(w, w);
#pragma unroll
                    for (int f = 0; f < NFULL; f++)
                        numP[p][f] = fma2(w2, halves[f], numP[p][f]);
                    if constexpr (ODD) numP[p][NFULL] = fma2(w2, tailv, numP[p][NFULL]);
                    else den[p] += w;
                }
            }
        }
    }

    // exact tiling: no bounds checks needed
    const int gyb = blockIdx.y * TH + row0;
    const int gxb = blockIdx.x * TW + c0;
#pragma unroll
    for (int py = 0; py < 2; py++)
#pragma unroll
    for (int px = 0; px < 2; px++) {
        const int p = py * 2 + px;
        float o[DYN + 1];
        float dn;
#pragma unroll
        for (int f = 0; f < NFULL; f++) unpack2(numP[p][f], o[2 * f], o[2 * f + 1]);
        if constexpr (ODD) { unpack2(numP[p][NFULL], o[DYN - 1], dn); }
        else dn = den[p];
        float rd;
        asm("rcp.approx.ftz.f32 %0, %1;" : "=f"(rd) : "f"(dn));
        float* op = out + (((size_t)b * DYN) * Hc + (gyb + 2 * py)) * Wc + (gxb + 2 * px);
#pragma unroll
        for (int c = 0; c < DYN; c++) op[(size_t)c * Hc * Wc] = o[c] * rd;
    }
}

extern "C" void kernel_launch(void* const* d_in, const int* in_sizes, int n_in,
                              void* d_out, int out_size) {
    const float* inp    = (const float*)d_in[0];
    const float* params = (const float*)d_in[1];
    const float* kern   = (const float*)d_in[2];
    float* out = (float*)d_out;
    (void)in_sizes; (void)n_in;

    int dyn = out_size / (Bc * Hc * Wc);
    if (dyn < 1) dyn = 1;
    if (dyn > 8) dyn = 8;

    bf_setup<<<1, 32>>>(params, kern);

    dim3 grid(Wc / TW, (Hc + TH - 1) / TH, Bc);

#define BF_LAUNCH(D)                                                                     \
    {                                                                                    \
        cudaFuncSetAttribute(bf_main<D>, cudaFuncAttributeMaxDynamicSharedMemorySize,    \
                             SMEM_BYTES);                                                \
        bf_main<D><<<grid, 256, SMEM_BYTES>>>(inp, out);                                 \
    }

    switch (dyn) {
        case 1: BF_LAUNCH(1); break;
        case 2: BF_LAUNCH(2); break;
        case 3: BF_LAUNCH(3); break;
        case 4: BF_LAUNCH(4); break;
        case 5: BF_LAUNCH(5); break;
        case 6: BF_LAUNCH(6); break;
        case 7: BF_LAUNCH(7); break;
        case 8: BF_LAUNCH(8); break;
        default: BF_LAUNCH(3); break;
    }
#undef BF_LAUNCH
}